// round 1
// baseline (speedup 1.0000x reference)
#include <cuda_runtime.h>

// ---------------- problem constants (all static) ----------------
#define NHEAD  8
#define HDIM   32
#define CD     256
#define HWDIM  56
#define NTOK   49      // 7*7
#define BWIN   1024    // 16 batches * 64 windows
#define MROWS  50176   // BWIN * NTOK  (divisible by 64: 784 tiles)

// ---------------- scratch (device globals; no allocs) ----------------
__device__ float g_q[BWIN * NHEAD * NTOK * HDIM];
__device__ float g_k[BWIN * NHEAD * NTOK * HDIM];
__device__ float g_v[BWIN * NHEAD * NTOK * HDIM];
__device__ float g_ao[MROWS * CD];

// ---------------- helpers ----------------
__device__ __forceinline__ unsigned f2tf(float f) {
    unsigned u;
    asm("cvt.rna.tf32.f32 %0, %1;" : "=r"(u) : "f"(f));
    return u;
}

__device__ __forceinline__ void mma8(float* c, const unsigned* a, const unsigned* b) {
    asm volatile(
        "mma.sync.aligned.m16n8k8.row.col.f32.tf32.tf32.f32 "
        "{%0,%1,%2,%3},{%4,%5,%6,%7},{%8,%9},{%0,%1,%2,%3};"
        : "+f"(c[0]), "+f"(c[1]), "+f"(c[2]), "+f"(c[3])
        : "r"(a[0]), "r"(a[1]), "r"(a[2]), "r"(a[3]), "r"(b[0]), "r"(b[1]));
}

// ============================================================
// Kernel 1: QKV GEMM (M=50176, N=768, K=256), gather fused.
// Block tile 64x64, 4 warps, warp tile 32x32 (2x4 m16n8k8 atoms).
// ============================================================
__global__ void __launch_bounds__(128) qkv_gemm(
    const float* __restrict__ Q, const float* __restrict__ Wq,
    const float* __restrict__ Bq)
{
    __shared__ unsigned As[64][36];   // pad 36: conflict-free frag reads
    __shared__ unsigned Bs[32][68];   // pad 68
    __shared__ int rsrc[64];

    const int tid = threadIdx.x;
    const int m0 = blockIdx.x * 64;
    const int n0 = blockIdx.y * 64;

    if (tid < 64) {
        int m   = m0 + tid;
        int win = m / 49, n = m - win * 49;
        int b = win >> 6, wy = (win >> 3) & 7, wx = win & 7;
        int iy = n / 7, ix = n - iy * 7;
        int y = wy * 7 + iy + 3; if (y >= 56) y -= 56;   // roll(-3) gather
        int x = wx * 7 + ix + 3; if (x >= 56) x -= 56;
        rsrc[tid] = ((b * 56 + y) * 56 + x) * 256;
    }

    float acc[2][4][4];
#pragma unroll
    for (int i = 0; i < 2; i++)
#pragma unroll
        for (int j = 0; j < 4; j++)
#pragma unroll
            for (int l = 0; l < 4; l++) acc[i][j][l] = 0.f;

    const int warp = tid >> 5, lane = tid & 31;
    const int g = lane >> 2, tg = lane & 3;
    const int wm = warp >> 1, wn = warp & 1;

    __syncthreads();

    for (int k0 = 0; k0 < 256; k0 += 32) {
#pragma unroll
        for (int t = 0; t < 4; t++) {                 // A: 64x32 fp32
            int idx = tid + t * 128;
            int r = idx >> 3, c = (idx & 7) << 2;
            float4 v = *(const float4*)(Q + rsrc[r] + k0 + c);
            uint4 u = make_uint4(f2tf(v.x), f2tf(v.y), f2tf(v.z), f2tf(v.w));
            *(uint4*)&As[r][c] = u;
        }
#pragma unroll
        for (int t = 0; t < 4; t++) {                 // B: 32x64 from w_qkv[256][768]
            int idx = tid + t * 128;
            int kk = idx >> 4, c = (idx & 15) << 2;
            float4 v = *(const float4*)(Wq + (k0 + kk) * 768 + n0 + c);
            uint4 u = make_uint4(f2tf(v.x), f2tf(v.y), f2tf(v.z), f2tf(v.w));
            *(uint4*)&Bs[kk][c] = u;
        }
        __syncthreads();

#pragma unroll
        for (int ka = 0; ka < 4; ka++) {
            unsigned a[2][4], bb[4][2];
#pragma unroll
            for (int ma = 0; ma < 2; ma++) {
                int r = wm * 32 + ma * 16 + g;
                a[ma][0] = As[r][ka * 8 + tg];
                a[ma][1] = As[r + 8][ka * 8 + tg];
                a[ma][2] = As[r][ka * 8 + tg + 4];
                a[ma][3] = As[r + 8][ka * 8 + tg + 4];
            }
#pragma unroll
            for (int na = 0; na < 4; na++) {
                int c = wn * 32 + na * 8 + g;
                bb[na][0] = Bs[ka * 8 + tg][c];
                bb[na][1] = Bs[ka * 8 + tg + 4][c];
            }
#pragma unroll
            for (int ma = 0; ma < 2; ma++)
#pragma unroll
                for (int na = 0; na < 4; na++) mma8(acc[ma][na], a[ma], bb[na]);
        }
        __syncthreads();
    }

    // epilogue: scatter into q/k/v [win][head][tok][d], q pre-scaled
    const float scale = 0.17677669529663687f;   // 32^-0.5
#pragma unroll
    for (int ma = 0; ma < 2; ma++) {
#pragma unroll
        for (int rr = 0; rr < 2; rr++) {
            int r = m0 + wm * 32 + ma * 16 + g + rr * 8;
            int win = r / 49, n = r - win * 49;
#pragma unroll
            for (int na = 0; na < 4; na++) {
                int c = n0 + wn * 32 + na * 8 + tg * 2;
                float v0 = acc[ma][na][rr * 2 + 0] + Bq[c];
                float v1 = acc[ma][na][rr * 2 + 1] + Bq[c + 1];
                int part = c >> 8;                   // 0=q 1=k 2=v (64 | 256)
                if (part == 0) { v0 *= scale; v1 *= scale; }
                int hh = (c >> 5) & 7, d = c & 31;
                float* dst = (part == 0) ? g_q : ((part == 1) ? g_k : g_v);
                *(float2*)(dst + (((win << 3) + hh) * 49 + n) * 32 + d) =
                    make_float2(v0, v1);
            }
        }
    }
}

// ============================================================
// Kernel 2: windowed attention, one block per (window, head).
// N=49, hd=32. Bias + shift mask computed analytically.
// ============================================================
__global__ void __launch_bounds__(64) attn_kernel(const float* __restrict__ rbt)
{
    const int bx = blockIdx.x;
    const int win = bx >> 3, h = bx & 7;

    __shared__ float qs[49 * 32], ks[49 * 32], vs[49 * 32];
    __shared__ float S[49][53];           // pad 53 -> conflict-free rows
    __shared__ float biasH[169];
    __shared__ int cnt[49];

    const int tid = threadIdx.x;
    const int base = ((win * 8 + h) * 49) * 32;
    const float* qp = g_q + base;
    const float* kp = g_k + base;
    const float* vp = g_v + base;

    for (int i = tid; i < 392; i += 64) {
        ((float4*)qs)[i] = ((const float4*)qp)[i];
        ((float4*)ks)[i] = ((const float4*)kp)[i];
        ((float4*)vs)[i] = ((const float4*)vp)[i];
    }
    for (int i = tid; i < 169; i += 64) biasH[i] = rbt[i * 8 + h];
    if (tid < 49) {
        int iy = tid / 7, ix = tid - iy * 7;
        int wy = (win >> 3) & 7, wx = win & 7;
        int y = wy * 7 + iy, x = wx * 7 + ix;
        int ry = y < 49 ? 0 : (y < 53 ? 1 : 2);
        int rx = x < 49 ? 0 : (x < 53 ? 1 : 2);
        cnt[tid] = ry * 3 + rx;
    }
    __syncthreads();

    if (tid < 49) {
        const int i = tid;
        float4 qr[8];
#pragma unroll
        for (int d = 0; d < 8; d++) qr[d] = ((const float4*)(qs + i * 32))[d];
        const int iy = i / 7, ix = i - iy * 7;
        const int ci = cnt[i];

        float mx = -1e30f;
        for (int j = 0; j < 49; j++) {
            float dot = 0.f;
#pragma unroll
            for (int d = 0; d < 8; d++) {
                float4 kv = ((const float4*)(ks + j * 32))[d];
                dot += qr[d].x * kv.x + qr[d].y * kv.y + qr[d].z * kv.z + qr[d].w * kv.w;
            }
            int jy = j / 7, jx = j - jy * 7;
            float s = dot + biasH[(iy - jy + 6) * 13 + (ix - jx + 6)];
            if (cnt[j] != ci) s -= 100.f;
            S[i][j] = s;
            mx = fmaxf(mx, s);
        }
        float sum = 0.f;
        for (int j = 0; j < 49; j++) {
            float e = __expf(S[i][j] - mx);
            S[i][j] = e;
            sum += e;
        }
        float inv = 1.f / sum;

        float4 o[8];
#pragma unroll
        for (int d = 0; d < 8; d++) o[d] = make_float4(0.f, 0.f, 0.f, 0.f);
        for (int j = 0; j < 49; j++) {
            float p = S[i][j];
#pragma unroll
            for (int d = 0; d < 8; d++) {
                float4 vv = ((const float4*)(vs + j * 32))[d];
                o[d].x += p * vv.x; o[d].y += p * vv.y;
                o[d].z += p * vv.z; o[d].w += p * vv.w;
            }
        }
        float* op = g_ao + (win * 49 + i) * 256 + h * 32;
#pragma unroll
        for (int d = 0; d < 8; d++)
            ((float4*)op)[d] = make_float4(o[d].x * inv, o[d].y * inv,
                                           o[d].z * inv, o[d].w * inv);
    }
}

// ============================================================
// Kernel 3: proj GEMM (M=50176, N=256, K=256) + window-reverse
// + roll-back scatter fused in the epilogue.
// ============================================================
__global__ void __launch_bounds__(128) proj_gemm(
    const float* __restrict__ Wp, const float* __restrict__ Bp,
    float* __restrict__ out)
{
    __shared__ unsigned As[64][36];
    __shared__ unsigned Bs[32][68];

    const int tid = threadIdx.x;
    const int m0 = blockIdx.x * 64;
    const int n0 = blockIdx.y * 64;

    float acc[2][4][4];
#pragma unroll
    for (int i = 0; i < 2; i++)
#pragma unroll
        for (int j = 0; j < 4; j++)
#pragma unroll
            for (int l = 0; l < 4; l++) acc[i][j][l] = 0.f;

    const int warp = tid >> 5, lane = tid & 31;
    const int g = lane >> 2, tg = lane & 3;
    const int wm = warp >> 1, wn = warp & 1;

    for (int k0 = 0; k0 < 256; k0 += 32) {
#pragma unroll
        for (int t = 0; t < 4; t++) {
            int idx = tid + t * 128;
            int r = idx >> 3, c = (idx & 7) << 2;
            float4 v = *(const float4*)(g_ao + (m0 + r) * 256 + k0 + c);
            uint4 u = make_uint4(f2tf(v.x), f2tf(v.y), f2tf(v.z), f2tf(v.w));
            *(uint4*)&As[r][c] = u;
        }
#pragma unroll
        for (int t = 0; t < 4; t++) {
            int idx = tid + t * 128;
            int kk = idx >> 4, c = (idx & 15) << 2;
            float4 v = *(const float4*)(Wp + (k0 + kk) * 256 + n0 + c);
            uint4 u = make_uint4(f2tf(v.x), f2tf(v.y), f2tf(v.z), f2tf(v.w));
            *(uint4*)&Bs[kk][c] = u;
        }
        __syncthreads();

#pragma unroll
        for (int ka = 0; ka < 4; ka++) {
            unsigned a[2][4], bb[4][2];
#pragma unroll
            for (int ma = 0; ma < 2; ma++) {
                int r = wm * 32 + ma * 16 + g;
                a[ma][0] = As[r][ka * 8 + tg];
                a[ma][1] = As[r + 8][ka * 8 + tg];
                a[ma][2] = As[r][ka * 8 + tg + 4];
                a[ma][3] = As[r + 8][ka * 8 + tg + 4];
            }
#pragma unroll
            for (int na = 0; na < 4; na++) {
                int c = wn * 32 + na * 8 + g;
                bb[na][0] = Bs[ka * 8 + tg][c];
                bb[na][1] = Bs[ka * 8 + tg + 4][c];
            }
#pragma unroll
            for (int ma = 0; ma < 2; ma++)
#pragma unroll
                for (int na = 0; na < 4; na++) mma8(acc[ma][na], a[ma], bb[na]);
        }
        __syncthreads();
    }

#pragma unroll
    for (int ma = 0; ma < 2; ma++) {
#pragma unroll
        for (int rr = 0; rr < 2; rr++) {
            int r = m0 + wm * 32 + ma * 16 + g + rr * 8;
            int win = r / 49, n = r - win * 49;
            int b = win >> 6, wy = (win >> 3) & 7, wx = win & 7;
            int iy = n / 7, ix = n - iy * 7;
            int y = wy * 7 + iy + 3; if (y >= 56) y -= 56;   // window-reverse + roll(+3)
            int x = wx * 7 + ix + 3; if (x >= 56) x -= 56;
            int obase = ((b * 56 + y) * 56 + x) * 256;
#pragma unroll
            for (int na = 0; na < 4; na++) {
                int c = n0 + wn * 32 + na * 8 + tg * 2;
                float v0 = acc[ma][na][rr * 2 + 0] + Bp[c];
                float v1 = acc[ma][na][rr * 2 + 1] + Bp[c + 1];
                *(float2*)(out + obase + c) = make_float2(v0, v1);
            }
        }
    }
}

// ============================================================
extern "C" void kernel_launch(void* const* d_in, const int* in_sizes, int n_in,
                              void* d_out, int out_size)
{
    const float* query = (const float*)d_in[0];
    const float* w_qkv = (const float*)d_in[1];
    const float* b_qkv = (const float*)d_in[2];
    const float* w_proj = (const float*)d_in[3];
    const float* b_proj = (const float*)d_in[4];
    const float* rbt   = (const float*)d_in[5];
    float* out = (float*)d_out;

    dim3 g1(784, 12);
    qkv_gemm<<<g1, 128>>>(query, w_qkv, b_qkv);

    attn_kernel<<<8192, 64>>>(rbt);

    dim3 g3(784, 4);
    proj_gemm<<<g3, 128>>>(w_proj, b_proj, out);
}